// round 13
// baseline (speedup 1.0000x reference)
#include <cuda_runtime.h>
#include <cstdint>
#include <cstddef>

// T=512, B=16, E=768, H=32, d=24, BH=512, M=T*B=8192
#define LOG2E 1.4426950408889634f

// ---------------------------------------------------------------------------
// Global scratch (no runtime allocation; __device__ globals, referenced ONLY
// from device code — never passed as kernel arguments from host)
// ---------------------------------------------------------------------------
__device__ float g_xh[8192 * 768];            // X (later attn out) hi plane, row-major
__device__ float g_xl[8192 * 768];            // lo plane
__device__ float g_wh[4 * 768 * 768];         // W{q,k,v,o} hi planes, row-major
__device__ float g_wl[4 * 768 * 768];
// Pre-split Q/K/V planes consumed by attention: [BH][T][24]
__device__ float g_qh[512 * 512 * 24];
__device__ float g_ql[512 * 512 * 24];
__device__ float g_kh[512 * 512 * 24];
__device__ float g_kl[512 * 512 * 24];
__device__ float g_vh[512 * 512 * 24];
__device__ float g_vl[512 * 512 * 24];
__device__ float g_attn[8192 * 768];          // [T*B][E]

// ---------------------------------------------------------------------------
// helpers
// ---------------------------------------------------------------------------
__device__ __forceinline__ void split_tf32(float x, uint32_t &h, uint32_t &l) {
    asm("cvt.rna.tf32.f32 %0, %1;" : "=r"(h) : "f"(x));
    float r = x - __uint_as_float(h);
    asm("cvt.rna.tf32.f32 %0, %1;" : "=r"(l) : "f"(r));
}
__device__ __forceinline__ void mma_tf32(float *c, const uint32_t *a, const uint32_t *b) {
    asm volatile(
        "mma.sync.aligned.m16n8k8.row.col.f32.tf32.tf32.f32 "
        "{%0,%1,%2,%3}, {%4,%5,%6,%7}, {%8,%9}, {%0,%1,%2,%3};"
        : "+f"(c[0]), "+f"(c[1]), "+f"(c[2]), "+f"(c[3])
        : "r"(a[0]), "r"(a[1]), "r"(a[2]), "r"(a[3]), "r"(b[0]), "r"(b[1]));
}
__device__ __forceinline__ void cpa16(float *s, const float *g) {
    uint32_t sa = (uint32_t)__cvta_generic_to_shared(s);
    asm volatile("cp.async.cg.shared.global [%0], [%1], 16;" :: "r"(sa), "l"(g));
}
__device__ __forceinline__ uint32_t fu(float x) { return __float_as_uint(x); }

// ---------------------------------------------------------------------------
// Split kernels: fp32 -> (tf32 hi, lo) planes, row-major.
// Device globals referenced DIRECTLY (not via host-passed pointers).
// ---------------------------------------------------------------------------
__global__ __launch_bounds__(256) void split_query(const float *__restrict__ src)
{
    size_t i = ((size_t)blockIdx.x * 256 + threadIdx.x) * 4;
    float4 v = *(const float4 *)(src + i);
    uint32_t h0, l0, h1, l1, h2, l2, h3, l3;
    split_tf32(v.x, h0, l0); split_tf32(v.y, h1, l1);
    split_tf32(v.z, h2, l2); split_tf32(v.w, h3, l3);
    *(float4 *)(g_xh + i) = make_float4(__uint_as_float(h0), __uint_as_float(h1),
                                        __uint_as_float(h2), __uint_as_float(h3));
    *(float4 *)(g_xl + i) = make_float4(__uint_as_float(l0), __uint_as_float(l1),
                                        __uint_as_float(l2), __uint_as_float(l3));
}

__global__ __launch_bounds__(256) void split_attnout()
{
    size_t i = ((size_t)blockIdx.x * 256 + threadIdx.x) * 4;
    float4 v = *(const float4 *)(g_attn + i);
    uint32_t h0, l0, h1, l1, h2, l2, h3, l3;
    split_tf32(v.x, h0, l0); split_tf32(v.y, h1, l1);
    split_tf32(v.z, h2, l2); split_tf32(v.w, h3, l3);
    *(float4 *)(g_xh + i) = make_float4(__uint_as_float(h0), __uint_as_float(h1),
                                        __uint_as_float(h2), __uint_as_float(h3));
    *(float4 *)(g_xl + i) = make_float4(__uint_as_float(l0), __uint_as_float(l1),
                                        __uint_as_float(l2), __uint_as_float(l3));
}

__global__ __launch_bounds__(256) void split_w(
    const float *__restrict__ w0, const float *__restrict__ w1,
    const float *__restrict__ w2, const float *__restrict__ w3)
{
    int mat = blockIdx.y;
    const float *src = (mat == 0) ? w0 : (mat == 1) ? w1 : (mat == 2) ? w2 : w3;
    size_t i = ((size_t)blockIdx.x * 256 + threadIdx.x) * 4;
    float4 v = *(const float4 *)(src + i);
    size_t o = (size_t)mat * (768 * 768) + i;
    uint32_t h0, l0, h1, l1, h2, l2, h3, l3;
    split_tf32(v.x, h0, l0); split_tf32(v.y, h1, l1);
    split_tf32(v.z, h2, l2); split_tf32(v.w, h3, l3);
    *(float4 *)(g_wh + o) = make_float4(__uint_as_float(h0), __uint_as_float(h1),
                                        __uint_as_float(h2), __uint_as_float(h3));
    *(float4 *)(g_wl + o) = make_float4(__uint_as_float(l0), __uint_as_float(l1),
                                        __uint_as_float(l2), __uint_as_float(l3));
}

// ---------------------------------------------------------------------------
// GEMM: C[M,N] = A[M,K] @ W[N,K]^T + bias, 3xTF32 from PRE-SPLIT planes.
// BM=128 BN=64 BK=24, STATIC SMEM 43KB, single-buffered (R1-proven config).
// Inner loop: pure LDS + MMA (no cvt/sub).
// MODE 0: QKV projection (blockIdx.z = matrix) -> split scatter [BH][T][24]
// MODE 1: output projection (mat 3, A = split g_attn) -> row-major out
// ---------------------------------------------------------------------------
template <int MODE>
__global__ __launch_bounds__(256, 2) void gemm3x(
    const float *__restrict__ bias0, const float *__restrict__ bias1,
    const float *__restrict__ bias2, float *__restrict__ outp)
{
    __shared__ float Ah[128][28];
    __shared__ float Al[128][28];
    __shared__ float Bh[64][28];
    __shared__ float Bl[64][28];

    const int tid = threadIdx.x;
    const int lane = tid & 31, wid = tid >> 5;
    const int g = lane >> 2, t = lane & 3;
    const int wm = wid & 3, wn = wid >> 2;
    const int m0 = blockIdx.y * 128, n0 = blockIdx.x * 64;
    const int mat = (MODE == 0) ? (int)blockIdx.z : 3;

    const float *bias = (MODE == 0)
        ? ((mat == 0) ? bias0 : (mat == 1) ? bias1 : bias2) : bias0;
    const float scale = (MODE == 0 && mat == 0) ? 0.2041241452319315f : 1.0f;

    const float *Wh = g_wh + (size_t)mat * (768 * 768);
    const float *Wl = g_wl + (size_t)mat * (768 * 768);

    float c[2][4][4];
#pragma unroll
    for (int mt = 0; mt < 2; mt++)
#pragma unroll
        for (int nt = 0; nt < 4; nt++)
#pragma unroll
            for (int j = 0; j < 4; j++) c[mt][nt][j] = 0.f;

    const int NIT = 768 / 24;  // 32
    for (int it = 0; it < NIT; it++) {
        const int kk = it * 24;
        __syncthreads();
        // A: 128 rows x 24 cols = 768 granules per plane
#pragma unroll
        for (int i = 0; i < 3; i++) {
            int idx = tid + i * 256;
            int r = idx / 6, c4 = (idx - r * 6) * 4;
            size_t go = (size_t)(m0 + r) * 768 + kk + c4;
            cpa16(&Ah[r][c4], g_xh + go);
            cpa16(&Al[r][c4], g_xl + go);
        }
        // B: 64 rows x 24 cols = 384 granules per plane
        for (int idx = tid; idx < 384; idx += 256) {
            int r = idx / 6, c4 = (idx - r * 6) * 4;
            size_t go = (size_t)(n0 + r) * 768 + kk + c4;
            cpa16(&Bh[r][c4], Wh + go);
            cpa16(&Bl[r][c4], Wl + go);
        }
        asm volatile("cp.async.commit_group;");
        asm volatile("cp.async.wait_group 0;");
        __syncthreads();

#pragma unroll
        for (int ks = 0; ks < 24; ks += 8) {
            uint32_t ah[2][4], al[2][4], bh[4][2], bl[4][2];
#pragma unroll
            for (int mt = 0; mt < 2; mt++) {
                int r = wm * 32 + mt * 16 + g;
                ah[mt][0] = fu(Ah[r][ks + t]);         al[mt][0] = fu(Al[r][ks + t]);
                ah[mt][1] = fu(Ah[r + 8][ks + t]);     al[mt][1] = fu(Al[r + 8][ks + t]);
                ah[mt][2] = fu(Ah[r][ks + t + 4]);     al[mt][2] = fu(Al[r][ks + t + 4]);
                ah[mt][3] = fu(Ah[r + 8][ks + t + 4]); al[mt][3] = fu(Al[r + 8][ks + t + 4]);
            }
#pragma unroll
            for (int nt = 0; nt < 4; nt++) {
                int n = wn * 32 + nt * 8 + g;
                bh[nt][0] = fu(Bh[n][ks + t]);     bl[nt][0] = fu(Bl[n][ks + t]);
                bh[nt][1] = fu(Bh[n][ks + t + 4]); bl[nt][1] = fu(Bl[n][ks + t + 4]);
            }
#pragma unroll
            for (int mt = 0; mt < 2; mt++)
#pragma unroll
                for (int nt = 0; nt < 4; nt++) {
                    mma_tf32(c[mt][nt], ah[mt], bh[nt]);
                    mma_tf32(c[mt][nt], al[mt], bh[nt]);
                    mma_tf32(c[mt][nt], ah[mt], bl[nt]);
                }
        }
    }

#pragma unroll
    for (int mt = 0; mt < 2; mt++) {
#pragma unroll
        for (int nt = 0; nt < 4; nt++) {
#pragma unroll
            for (int j = 0; j < 4; j++) {
                int m = m0 + wm * 32 + mt * 16 + g + ((j >> 1) ? 8 : 0);
                int n = n0 + wn * 32 + nt * 8 + 2 * t + (j & 1);
                float v = (c[mt][nt][j] + bias[n]) * scale;
                if (MODE == 0) {
                    int tt = m >> 4, bb = m & 15;           // m = t*16 + b
                    int h = n / 24, dd = n - h * 24;        // n = h*24 + dd
                    size_t idx = (((size_t)bb * 32 + h) * 512 + tt) * 24 + dd;
                    uint32_t hb, lb;
                    split_tf32(v, hb, lb);
                    float *dsth = (mat == 0) ? g_qh : (mat == 1) ? g_kh : g_vh;
                    float *dstl = (mat == 0) ? g_ql : (mat == 1) ? g_kl : g_vl;
                    dsth[idx] = __uint_as_float(hb);
                    dstl[idx] = __uint_as_float(lb);
                } else {
                    outp[(size_t)m * 768 + n] = v;
                }
            }
        }
    }
}

// ---------------------------------------------------------------------------
// Fused attention (byte-identical to R2-passing version).
// ---------------------------------------------------------------------------
#define ATTN_SMEM_FLOATS (2304*2 + 2304*8 + 4*16*68)
__global__ __launch_bounds__(128) void attn_kernel(const float *__restrict__ biasG)
{
    extern __shared__ float smf[];
    float (*Qh)[36] = (float (*)[36])(smf);
    float (*Ql)[36] = (float (*)[36])(smf + 2304);
    float (*Kh)[64][36] = (float (*)[64][36])(smf + 4608);
    float (*Kl)[64][36] = (float (*)[64][36])(smf + 4608 + 4608);
    float (*Vh)[64][36] = (float (*)[64][36])(smf + 4608 + 9216);
    float (*Vl)[64][36] = (float (*)[64][36])(smf + 4608 + 13824);
    float (*Ps)[16][68] = (float (*)[16][68])(smf + 4608 + 18432);

    const int tid = threadIdx.x;
    const int lane = tid & 31, wid = tid >> 5;
    const int g = lane >> 2, t = lane & 3;
    const int bh = blockIdx.x;
    const int q0 = blockIdx.y * 64;

    const size_t hb = (size_t)bh * (512 * 24);
    const float *Bp = biasG + (size_t)bh * (512 * 512);

    for (int i = tid; i < 384; i += 128) {
        int r = i / 6, c4 = (i - r * 6) * 4;
        cpa16(&Qh[r][c4], g_qh + hb + (size_t)(q0 + r) * 24 + c4);
        cpa16(&Ql[r][c4], g_ql + hb + (size_t)(q0 + r) * 24 + c4);
    }
    asm volatile("cp.async.commit_group;");

    auto ldkv = [&](int s0, int st) {
        for (int i = tid; i < 384; i += 128) {
            int r = i / 6, c4 = (i - r * 6) * 4;
            size_t off = hb + (size_t)(s0 + r) * 24 + c4;
            cpa16(&Kh[st][r][c4], g_kh + off);
            cpa16(&Kl[st][r][c4], g_kl + off);
            cpa16(&Vh[st][r][c4], g_vh + off);
            cpa16(&Vl[st][r][c4], g_vl + off);
        }
        asm volatile("cp.async.commit_group;");
    };

    ldkv(0, 0);
    asm volatile("cp.async.wait_group 1;");
    __syncthreads();

    uint32_t qh[3][4], ql[3][4];
    {
        int r = wid * 16 + g;
#pragma unroll
        for (int ks = 0; ks < 3; ks++) {
            int kc = ks * 8 + t;
            qh[ks][0] = fu(Qh[r][kc]);         ql[ks][0] = fu(Ql[r][kc]);
            qh[ks][1] = fu(Qh[r + 8][kc]);     ql[ks][1] = fu(Ql[r + 8][kc]);
            qh[ks][2] = fu(Qh[r][kc + 4]);     ql[ks][2] = fu(Ql[r][kc + 4]);
            qh[ks][3] = fu(Qh[r + 8][kc + 4]); ql[ks][3] = fu(Ql[r + 8][kc + 4]);
        }
    }

    float mrow0 = -1e30f, mrow1 = -1e30f;
    float lrow0 = 0.f, lrow1 = 0.f;
    float o[3][4];
#pragma unroll
    for (int vt = 0; vt < 3; vt++)
#pragma unroll
        for (int j = 0; j < 4; j++) o[vt][j] = 0.f;

    const int rg0 = q0 + wid * 16 + g;

    for (int it = 0; it < 8; it++) {
        const int st = it & 1;
        const int s0 = it * 64;
        if (it + 1 < 8) {
            ldkv((it + 1) * 64, st ^ 1);
            asm volatile("cp.async.wait_group 1;");
        } else {
            asm volatile("cp.async.wait_group 0;");
        }
        __syncthreads();

        float s[8][4];
        const float *Bq0 = Bp + (size_t)rg0 * 512 + s0 + 2 * t;
        const float *Bq1 = Bp + (size_t)(rg0 + 8) * 512 + s0 + 2 * t;
#pragma unroll
        for (int nt = 0; nt < 8; nt++) {
            const float2 u0 = *(const float2 *)(Bq0 + nt * 8);
            const float2 u1 = *(const float2 *)(Bq1 + nt * 8);
            s[nt][0] = u0.x; s[nt][1] = u0.y;
            s[nt][2] = u1.x; s[nt][3] = u1.y;
        }

#pragma unroll
        for (int ks = 0; ks < 3; ks++) {
            const int kc = ks * 8 + t;
#pragma unroll
            for (int nt = 0; nt < 8; nt++) {
                const int n = nt * 8 + g;
                uint32_t kbh[2] = { fu(Kh[st][n][kc]), fu(Kh[st][n][kc + 4]) };
                uint32_t kbl[2] = { fu(Kl[st][n][kc]), fu(Kl[st][n][kc + 4]) };
                mma_tf32(s[nt], qh[ks], kbh);
                mma_tf32(s[nt], ql[ks], kbh);
                mma_tf32(s[nt], qh[ks], kbl);
            }
        }

        float tm0 = -1e30f, tm1 = -1e30f;
#pragma unroll
        for (int nt = 0; nt < 8; nt++) {
            tm0 = fmaxf(tm0, fmaxf(s[nt][0], s[nt][1]));
            tm1 = fmaxf(tm1, fmaxf(s[nt][2], s[nt][3]));
        }
        tm0 = fmaxf(tm0, __shfl_xor_sync(0xffffffffu, tm0, 1));
        tm0 = fmaxf(tm0, __shfl_xor_sync(0xffffffffu, tm0, 2));
        tm1 = fmaxf(tm1, __shfl_xor_sync(0xffffffffu, tm1, 1));
        tm1 = fmaxf(tm1, __shfl_xor_sync(0xffffffffu, tm1, 2));
        float mn0 = fmaxf(mrow0, tm0), mn1 = fmaxf(mrow1, tm1);
        float al0 = exp2f((mrow0 - mn0) * LOG2E);
        float al1 = exp2f((mrow1 - mn1) * LOG2E);
        float sum0 = 0.f, sum1 = 0.f;
#pragma unroll
        for (int nt = 0; nt < 8; nt++) {
            s[nt][0] = exp2f((s[nt][0] - mn0) * LOG2E);
            s[nt][1] = exp2f((s[nt][1] - mn0) * LOG2E);
            s[nt][2] = exp2f((s[nt][2] - mn1) * LOG2E);
            s[nt][3] = exp2f((s[nt][3] - mn1) * LOG2E);
            sum0 += s[nt][0] + s[nt][1];
            sum1 += s[nt][2] + s[nt][3];
        }
        sum0 += __shfl_xor_sync(0xffffffffu, sum0, 1);
        sum0 += __shfl_xor_sync(0xffffffffu, sum0, 2);
        sum1 += __shfl_xor_sync(0xffffffffu, sum1, 1);
        sum1 += __shfl_xor_sync(0xffffffffu, sum1, 2);
        lrow0 = lrow0 * al0 + sum0;
        lrow1 = lrow1 * al1 + sum1;
        mrow0 = mn0; mrow1 = mn1;
#pragma unroll
        for (int vt = 0; vt < 3; vt++) {
            o[vt][0] *= al0; o[vt][1] *= al0;
            o[vt][2] *= al1; o[vt][3] *= al1;
        }

#pragma unroll
        for (int nt = 0; nt < 8; nt++) {
            *(float2 *)&Ps[wid][g][nt * 8 + 2 * t]     = make_float2(s[nt][0], s[nt][1]);
            *(float2 *)&Ps[wid][g + 8][nt * 8 + 2 * t] = make_float2(s[nt][2], s[nt][3]);
        }
        __syncwarp();

#pragma unroll
        for (int ks = 0; ks < 8; ks++) {
            const int kc = ks * 8 + t;
            uint32_t ah2[4], al2[4];
            split_tf32(Ps[wid][g][kc],         ah2[0], al2[0]);
            split_tf32(Ps[wid][g + 8][kc],     ah2[1], al2[1]);
            split_tf32(Ps[wid][g][kc + 4],     ah2[2], al2[2]);
            split_tf32(Ps[wid][g + 8][kc + 4], ah2[3], al2[3]);
#pragma unroll
            for (int vt = 0; vt < 3; vt++) {
                uint32_t vbh[2] = { fu(Vh[st][kc][vt * 8 + g]), fu(Vh[st][kc + 4][vt * 8 + g]) };
                uint32_t vbl[2] = { fu(Vl[st][kc][vt * 8 + g]), fu(Vl[st][kc + 4][vt * 8 + g]) };
                mma_tf32(o[vt], ah2, vbh);
                mma_tf32(o[vt], al2, vbh);
                mma_tf32(o[vt], ah2, vbl);
            }
        }
        __syncthreads();
    }

    float inv0 = 1.f / lrow0;
    float inv1 = 1.f / lrow1;
    int tq = q0 + wid * 16 + g;
    int b_ = bh >> 5, hh = bh & 31;
#pragma unroll
    for (int vt = 0; vt < 3; vt++) {
        int col = hh * 24 + vt * 8 + 2 * t;
        float *d0 = &g_attn[((size_t)tq * 16 + b_) * 768 + col];
        d0[0] = o[vt][0] * inv0;
        d0[1] = o[vt][1] * inv0;
        float *d1 = &g_attn[((size_t)(tq + 8) * 16 + b_) * 768 + col];
        d1[0] = o[vt][2] * inv1;
        d1[1] = o[vt][3] * inv1;
    }
}

// ---------------------------------------------------------------------------
extern "C" void kernel_launch(void *const *d_in, const int *in_sizes, int n_in,
                              void *d_out, int out_size)
{
    const float *query = (const float *)d_in[0];
    const float *attn_bias = (const float *)d_in[1];
    const float *Wq = (const float *)d_in[2];
    const float *bq = (const float *)d_in[3];
    const float *Wk = (const float *)d_in[4];
    const float *bk = (const float *)d_in[5];
    const float *Wv = (const float *)d_in[6];
    const float *bv = (const float *)d_in[7];
    const float *Wo = (const float *)d_in[8];
    const float *bo = (const float *)d_in[9];
    float *out = (float *)d_out;

    const int attn_smem = ATTN_SMEM_FLOATS * 4;   // ~107 KB (proven in R2)
    cudaFuncSetAttribute(attn_kernel, cudaFuncAttributeMaxDynamicSharedMemorySize, attn_smem);

    // split X and weights into tf32 hi/lo planes (globals referenced in-device)
    split_query<<<6144, 256>>>(query);
    split_w<<<dim3(576, 4), 256>>>(Wq, Wk, Wv, Wo);

    // QKV projection (static 43KB SMEM)
    gemm3x<0><<<dim3(12, 64, 3), 256>>>(bq, bk, bv, nullptr);

    // fused attention
    attn_kernel<<<dim3(512, 8), 128, attn_smem>>>(attn_bias);

    // re-split attention output (reads g_attn directly)
    split_attnout<<<6144, 256>>>();

    // output projection
    gemm3x<1><<<dim3(12, 64, 1), 256>>>(bo, nullptr, nullptr, out);
}

// round 15
// speedup vs baseline: 1.5516x; 1.5516x over previous
#include <cuda_runtime.h>
#include <cuda_bf16.h>
#include <cstdint>
#include <cstddef>

// T=512, B=16, E=768, H=32, d=24, BH=512, M=T*B=8192
#define LOG2E 1.4426950408889634f

// ---------------------------------------------------------------------------
// Global scratch (zero-initialized __device__ globals; referenced ONLY in
// device code — never passed as kernel args from host)
// ---------------------------------------------------------------------------
__device__ __nv_bfloat16 g_xh[8192 * 768];        // X / attn-out hi plane
__device__ __nv_bfloat16 g_xl[8192 * 768];        // lo plane
__device__ __nv_bfloat16 g_wh[4 * 768 * 768];     // W{q,k,v,o} hi planes
__device__ __nv_bfloat16 g_wl[4 * 768 * 768];
// Q,K planes [BH][T][32] (cols 24..31 stay zero forever), V transposed [BH][24][512]
__device__ __nv_bfloat16 g_qh[512 * 512 * 32];
__device__ __nv_bfloat16 g_ql[512 * 512 * 32];
__device__ __nv_bfloat16 g_kh[512 * 512 * 32];
__device__ __nv_bfloat16 g_kl[512 * 512 * 32];
__device__ __nv_bfloat16 g_vh[512 * 24 * 512];
__device__ __nv_bfloat16 g_vl[512 * 24 * 512];
__device__ float g_attn[8192 * 768];              // [T*B][E] fp32

// ---------------------------------------------------------------------------
// helpers
// ---------------------------------------------------------------------------
__device__ __forceinline__ uint32_t bpack(float hi, float lo) {
    uint32_t r;
    asm("cvt.rn.bf16x2.f32 %0, %1, %2;" : "=r"(r) : "f"(hi), "f"(lo));
    return r;
}
// split (x0,x1) -> packed hi plane {x1h,x0h} and lo plane {x1l,x0l}
__device__ __forceinline__ void bsplit2(float x0, float x1, uint32_t &h, uint32_t &l) {
    h = bpack(x1, x0);
    float r0 = x0 - __uint_as_float(h << 16);
    float r1 = x1 - __uint_as_float(h & 0xffff0000u);
    l = bpack(r1, r0);
}
__device__ __forceinline__ void mma_bf16(float *c, const uint32_t *a, const uint32_t *b) {
    asm volatile(
        "mma.sync.aligned.m16n8k16.row.col.f32.bf16.bf16.f32 "
        "{%0,%1,%2,%3}, {%4,%5,%6,%7}, {%8,%9}, {%0,%1,%2,%3};"
        : "+f"(c[0]), "+f"(c[1]), "+f"(c[2]), "+f"(c[3])
        : "r"(a[0]), "r"(a[1]), "r"(a[2]), "r"(a[3]), "r"(b[0]), "r"(b[1]));
}
__device__ __forceinline__ void cpa16(void *s, const void *g) {
    uint32_t sa = (uint32_t)__cvta_generic_to_shared(s);
    asm volatile("cp.async.cg.shared.global [%0], [%1], 16;" :: "r"(sa), "l"(g));
}
__device__ __forceinline__ uint32_t U32(const __nv_bfloat16 *p) {
    return *(const uint32_t *)p;
}

// ---------------------------------------------------------------------------
// Split kernels: fp32 -> (bf16 hi, lo) planes
// ---------------------------------------------------------------------------
__global__ __launch_bounds__(256) void split_query(const float *__restrict__ src)
{
    size_t i = ((size_t)blockIdx.x * 256 + threadIdx.x) * 4;
    float4 v = *(const float4 *)(src + i);
    uint32_t h01, l01, h23, l23;
    bsplit2(v.x, v.y, h01, l01);
    bsplit2(v.z, v.w, h23, l23);
    *(uint2 *)&g_xh[i] = make_uint2(h01, h23);
    *(uint2 *)&g_xl[i] = make_uint2(l01, l23);
}

__global__ __launch_bounds__(256) void split_attnout()
{
    size_t i = ((size_t)blockIdx.x * 256 + threadIdx.x) * 4;
    float4 v = *(const float4 *)(g_attn + i);
    uint32_t h01, l01, h23, l23;
    bsplit2(v.x, v.y, h01, l01);
    bsplit2(v.z, v.w, h23, l23);
    *(uint2 *)&g_xh[i] = make_uint2(h01, h23);
    *(uint2 *)&g_xl[i] = make_uint2(l01, l23);
}

__global__ __launch_bounds__(256) void split_w(
    const float *__restrict__ w0, const float *__restrict__ w1,
    const float *__restrict__ w2, const float *__restrict__ w3)
{
    int mat = blockIdx.y;
    const float *src = (mat == 0) ? w0 : (mat == 1) ? w1 : (mat == 2) ? w2 : w3;
    size_t i = ((size_t)blockIdx.x * 256 + threadIdx.x) * 4;
    float4 v = *(const float4 *)(src + i);
    size_t o = (size_t)mat * (768 * 768) + i;
    uint32_t h01, l01, h23, l23;
    bsplit2(v.x, v.y, h01, l01);
    bsplit2(v.z, v.w, h23, l23);
    *(uint2 *)&g_wh[o] = make_uint2(h01, h23);
    *(uint2 *)&g_wl[o] = make_uint2(l01, l23);
}

// ---------------------------------------------------------------------------
// GEMM: C[M,N] = A[M,K] @ W[N,K]^T + bias, 3xBF16 (m16n8k16).
// BM=128 BN=64 BK=32, static SMEM 30KB single-buffered, pure LDS+MMA inner.
// MODE 0: QKV projection (blockIdx.z = matrix) -> split planes
//         Q/K: [BH][T][32], V: transposed [BH][24][512]
// MODE 1: output projection (mat 3) -> row-major fp32 out
// ---------------------------------------------------------------------------
template <int MODE>
__global__ __launch_bounds__(256, 2) void gemm3x(
    const float *__restrict__ bias0, const float *__restrict__ bias1,
    const float *__restrict__ bias2, float *__restrict__ outp)
{
    __shared__ __nv_bfloat16 Ah[128][40];
    __shared__ __nv_bfloat16 Al[128][40];
    __shared__ __nv_bfloat16 Bh[64][40];
    __shared__ __nv_bfloat16 Bl[64][40];

    const int tid = threadIdx.x;
    const int lane = tid & 31, wid = tid >> 5;
    const int g = lane >> 2, t = lane & 3;
    const int wm = wid & 3, wn = wid >> 2;
    const int m0 = blockIdx.y * 128, n0 = blockIdx.x * 64;
    const int mat = (MODE == 0) ? (int)blockIdx.z : 3;

    const float *bias = (MODE == 0)
        ? ((mat == 0) ? bias0 : (mat == 1) ? bias1 : bias2) : bias0;
    const float scale = (MODE == 0 && mat == 0) ? 0.2041241452319315f : 1.0f;

    const __nv_bfloat16 *Wh = g_wh + (size_t)mat * (768 * 768);
    const __nv_bfloat16 *Wl = g_wl + (size_t)mat * (768 * 768);

    float c[2][4][4];
#pragma unroll
    for (int mt = 0; mt < 2; mt++)
#pragma unroll
        for (int nt = 0; nt < 4; nt++)
#pragma unroll
            for (int j = 0; j < 4; j++) c[mt][nt][j] = 0.f;

    for (int it = 0; it < 24; it++) {
        const int kk = it * 32;
        __syncthreads();
        // A: 128 rows x 32 bf16 = 4 granules/row -> 512 per plane
#pragma unroll
        for (int i = 0; i < 2; i++) {
            int idx = tid + i * 256;
            int r = idx >> 2, c8 = (idx & 3) * 8;
            size_t go = (size_t)(m0 + r) * 768 + kk + c8;
            cpa16(&Ah[r][c8], g_xh + go);
            cpa16(&Al[r][c8], g_xl + go);
        }
        // B: 64 rows -> 256 granules per plane (1 per thread)
        {
            int r = tid >> 2, c8 = (tid & 3) * 8;
            size_t go = (size_t)(n0 + r) * 768 + kk + c8;
            cpa16(&Bh[r][c8], Wh + go);
            cpa16(&Bl[r][c8], Wl + go);
        }
        asm volatile("cp.async.commit_group;");
        asm volatile("cp.async.wait_group 0;");
        __syncthreads();

#pragma unroll
        for (int ks = 0; ks < 32; ks += 16) {
            const int cbase = ks + 2 * t;
            uint32_t ah[2][4], al[2][4], bh[4][2], bl[4][2];
#pragma unroll
            for (int mt = 0; mt < 2; mt++) {
                int r = wm * 32 + mt * 16 + g;
                ah[mt][0] = U32(&Ah[r][cbase]);         al[mt][0] = U32(&Al[r][cbase]);
                ah[mt][1] = U32(&Ah[r + 8][cbase]);     al[mt][1] = U32(&Al[r + 8][cbase]);
                ah[mt][2] = U32(&Ah[r][cbase + 8]);     al[mt][2] = U32(&Al[r][cbase + 8]);
                ah[mt][3] = U32(&Ah[r + 8][cbase + 8]); al[mt][3] = U32(&Al[r + 8][cbase + 8]);
            }
#pragma unroll
            for (int nt = 0; nt < 4; nt++) {
                int n = wn * 32 + nt * 8 + g;
                bh[nt][0] = U32(&Bh[n][cbase]);     bl[nt][0] = U32(&Bl[n][cbase]);
                bh[nt][1] = U32(&Bh[n][cbase + 8]); bl[nt][1] = U32(&Bl[n][cbase + 8]);
            }
#pragma unroll
            for (int mt = 0; mt < 2; mt++)
#pragma unroll
                for (int nt = 0; nt < 4; nt++) {
                    mma_bf16(c[mt][nt], ah[mt], bh[nt]);
                    mma_bf16(c[mt][nt], al[mt], bh[nt]);
                    mma_bf16(c[mt][nt], ah[mt], bl[nt]);
                }
        }
    }

#pragma unroll
    for (int mt = 0; mt < 2; mt++) {
#pragma unroll
        for (int nt = 0; nt < 4; nt++) {
#pragma unroll
            for (int j = 0; j < 4; j++) {
                int m = m0 + wm * 32 + mt * 16 + g + ((j >> 1) ? 8 : 0);
                int n = n0 + wn * 32 + nt * 8 + 2 * t + (j & 1);
                float v = (c[mt][nt][j] + bias[n]) * scale;
                if (MODE == 0) {
                    int tt = m >> 4, bb = m & 15;           // m = t*16 + b
                    int h = n / 24, dd = n - h * 24;        // n = h*24 + dd
                    __nv_bfloat16 hb = __float2bfloat16(v);
                    __nv_bfloat16 lb = __float2bfloat16(v - __bfloat162float(hb));
                    if (mat == 2) {   // V transposed [BH][24][512]
                        size_t idx = (((size_t)bb * 32 + h) * 24 + dd) * 512 + tt;
                        g_vh[idx] = hb; g_vl[idx] = lb;
                    } else {          // Q/K [BH][T][32]
                        size_t idx = (((size_t)bb * 32 + h) * 512 + tt) * 32 + dd;
                        if (mat == 0) { g_qh[idx] = hb; g_ql[idx] = lb; }
                        else          { g_kh[idx] = hb; g_kl[idx] = lb; }
                    }
                } else {
                    outp[(size_t)m * 768 + n] = v;
                }
            }
        }
    }
}

// ---------------------------------------------------------------------------
// Fused attention, 3xBF16. 256 threads, 128 q-rows per CTA (8 warps x 16 rows),
// K/V tiles (64 s-rows) shared by all warps; 2-stage cp.async KV pipeline.
// Dynamic SMEM (bf16 elems):
//  QH[128][40]@0      QL@5120
//  KH[2][64][40]@10240 KL@15360
//  VTH[2][24][72]@20480 VTL@23936
//  PSH[8][16][72]@27392 PSL@36608      total 45824 elems = 91648 B
// ---------------------------------------------------------------------------
#define ATTN_SMEM_BYTES (45824 * 2)
#define QH_(r, c)      smb[(r) * 40 + (c)]
#define QL_(r, c)      smb[5120 + (r) * 40 + (c)]
#define KH_(st, r, c)  smb[10240 + ((st) * 64 + (r)) * 40 + (c)]
#define KL_(st, r, c)  smb[15360 + ((st) * 64 + (r)) * 40 + (c)]
#define VTH_(st, r, c) smb[20480 + ((st) * 24 + (r)) * 72 + (c)]
#define VTL_(st, r, c) smb[23936 + ((st) * 24 + (r)) * 72 + (c)]
#define PSH_(w, r, c)  smb[27392 + ((w) * 16 + (r)) * 72 + (c)]
#define PSL_(w, r, c)  smb[36608 + ((w) * 16 + (r)) * 72 + (c)]

__global__ __launch_bounds__(256) void attn_kernel(const float *__restrict__ biasG)
{
    extern __shared__ __nv_bfloat16 smb[];

    const int tid = threadIdx.x;
    const int lane = tid & 31, wid = tid >> 5;
    const int g = lane >> 2, t = lane & 3;
    const int bh = blockIdx.x;
    const int q0 = blockIdx.y * 128;

    const size_t hqk = (size_t)bh * (512 * 32);
    const size_t hv = (size_t)bh * (24 * 512);
    const float *Bp = biasG + (size_t)bh * (512 * 512);

    // Q planes: 128 rows x 32 bf16 = 512 granules per plane
    for (int i = tid; i < 512; i += 256) {
        int r = i >> 2, c8 = (i & 3) * 8;
        size_t go = hqk + (size_t)(q0 + r) * 32 + c8;
        cpa16(&QH_(r, c8), g_qh + go);
        cpa16(&QL_(r, c8), g_ql + go);
    }
    asm volatile("cp.async.commit_group;");

    auto ldkv = [&](int s0, int st) {
        for (int i = tid; i < 256; i += 256) {
            int r = i >> 2, c8 = (i & 3) * 8;
            size_t go = hqk + (size_t)(s0 + r) * 32 + c8;
            cpa16(&KH_(st, r, c8), g_kh + go);
            cpa16(&KL_(st, r, c8), g_kl + go);
        }
        if (tid < 192) {
            int r = tid >> 3, c8 = (tid & 7) * 8;
            size_t go = hv + (size_t)r * 512 + s0 + c8;
            cpa16(&VTH_(st, r, c8), g_vh + go);
            cpa16(&VTL_(st, r, c8), g_vl + go);
        }
        asm volatile("cp.async.commit_group;");
    };

    ldkv(0, 0);
    asm volatile("cp.async.wait_group 1;");   // Q done (KV0 may be pending)
    __syncthreads();

    // Q fragments are loop-invariant: 2 k16-steps cover d=24 (pad zero)
    uint32_t qh[2][4], ql[2][4];
    {
        int r = wid * 16 + g;
#pragma unroll
        for (int ks = 0; ks < 2; ks++) {
            int c = ks * 16 + 2 * t;
            qh[ks][0] = U32(&QH_(r, c));         ql[ks][0] = U32(&QL_(r, c));
            qh[ks][1] = U32(&QH_(r + 8, c));     ql[ks][1] = U32(&QL_(r + 8, c));
            qh[ks][2] = U32(&QH_(r, c + 8));     ql[ks][2] = U32(&QL_(r, c + 8));
            qh[ks][3] = U32(&QH_(r + 8, c + 8)); ql[ks][3] = U32(&QL_(r + 8, c + 8));
        }
    }

    float mrow0 = -1e30f, mrow1 = -1e30f;
    float lrow0 = 0.f, lrow1 = 0.f;
    float o[3][4];
#pragma unroll
    for (int vt = 0; vt < 3; vt++)
#pragma unroll
        for (int j = 0; j < 4; j++) o[vt][j] = 0.f;

    const int rg0 = q0 + wid * 16 + g;

    for (int it = 0; it < 8; it++) {
        const int st = it & 1;
        const int s0 = it * 64;
        if (it + 1 < 8) {
            ldkv((it + 1) * 64, st ^ 1);
            asm volatile("cp.async.wait_group 1;");
        } else {
            asm volatile("cp.async.wait_group 0;");
        }
        __syncthreads();

        // bias -> accumulator init
        float s[8][4];
        const float *Bq0 = Bp + (size_t)rg0 * 512 + s0 + 2 * t;
        const float *Bq1 = Bp + (size_t)(rg0 + 8) * 512 + s0 + 2 * t;
#pragma unroll
        for (int nt = 0; nt < 8; nt++) {
            const float2 u0 = *(const float2 *)(Bq0 + nt * 8);
            const float2 u1 = *(const float2 *)(Bq1 + nt * 8);
            s[nt][0] = u0.x; s[nt][1] = u0.y;
            s[nt][2] = u1.x; s[nt][3] = u1.y;
        }

        // S += Q K^T (3xBF16, 2 k16-steps)
#pragma unroll
        for (int ks = 0; ks < 2; ks++) {
            const int c = ks * 16 + 2 * t;
#pragma unroll
            for (int nt = 0; nt < 8; nt++) {
                const int n = nt * 8 + g;
                uint32_t kbh[2] = { U32(&KH_(st, n, c)), U32(&KH_(st, n, c + 8)) };
                uint32_t kbl[2] = { U32(&KL_(st, n, c)), U32(&KL_(st, n, c + 8)) };
                mma_bf16(s[nt], qh[ks], kbh);
                mma_bf16(s[nt], ql[ks], kbh);
                mma_bf16(s[nt], qh[ks], kbl);
            }
        }

        // online softmax (rows g, g+8 of this warp's 16-row slice)
        float tm0 = -1e30f, tm1 = -1e30f;
#pragma unroll
        for (int nt = 0; nt < 8; nt++) {
            tm0 = fmaxf(tm0, fmaxf(s[nt][0], s[nt][1]));
            tm1 = fmaxf(tm1, fmaxf(s[nt][2], s[nt][3]));
        }
        tm0 = fmaxf(tm0, __shfl_xor_sync(0xffffffffu, tm0, 1));
        tm0 = fmaxf(tm0, __shfl_xor_sync(0xffffffffu, tm0, 2));
        tm1 = fmaxf(tm1, __shfl_xor_sync(0xffffffffu, tm1, 1));
        tm1 = fmaxf(tm1, __shfl_xor_sync(0xffffffffu, tm1, 2));
        float mn0 = fmaxf(mrow0, tm0), mn1 = fmaxf(mrow1, tm1);
        float al0 = exp2f((mrow0 - mn0) * LOG2E);
        float al1 = exp2f((mrow1 - mn1) * LOG2E);
        float sum0 = 0.f, sum1 = 0.f;
#pragma unroll
        for (int nt = 0; nt < 8; nt++) {
            s[nt][0] = exp2f((s[nt][0] - mn0) * LOG2E);
            s[nt][1] = exp2f((s[nt][1] - mn0) * LOG2E);
            s[nt][2] = exp2f((s[nt][2] - mn1) * LOG2E);
            s[nt][3] = exp2f((s[nt][3] - mn1) * LOG2E);
            sum0 += s[nt][0] + s[nt][1];
            sum1 += s[nt][2] + s[nt][3];
        }
        sum0 += __shfl_xor_sync(0xffffffffu, sum0, 1);
        sum0 += __shfl_xor_sync(0xffffffffu, sum0, 2);
        sum1 += __shfl_xor_sync(0xffffffffu, sum1, 1);
        sum1 += __shfl_xor_sync(0xffffffffu, sum1, 2);
        lrow0 = lrow0 * al0 + sum0;
        lrow1 = lrow1 * al1 + sum1;
        mrow0 = mn0; mrow1 = mn1;
#pragma unroll
        for (int vt = 0; vt < 3; vt++) {
            o[vt][0] *= al0; o[vt][1] *= al0;
            o[vt][2] *= al1; o[vt][3] *= al1;
        }

        // P: split to bf16 hi/lo planes in per-warp SMEM region
#pragma unroll
        for (int nt = 0; nt < 8; nt++) {
            const int c = nt * 8 + 2 * t;
            uint32_t h0, l0, h1, l1;
            bsplit2(s[nt][0], s[nt][1], h0, l0);
            bsplit2(s[nt][2], s[nt][3], h1, l1);
            *(uint32_t *)&PSH_(wid, g, c) = h0;
            *(uint32_t *)&PSL_(wid, g, c) = l0;
            *(uint32_t *)&PSH_(wid, g + 8, c) = h1;
            *(uint32_t *)&PSL_(wid, g + 8, c) = l1;
        }
        __syncwarp();

        // O += P V (3xBF16, 4 k16-steps over s=64)
#pragma unroll
        for (int ks = 0; ks < 4; ks++) {
            const int c = ks * 16 + 2 * t;
            uint32_t ah2[4], al2[4];
            ah2[0] = U32(&PSH_(wid, g, c));         al2[0] = U32(&PSL_(wid, g, c));
            ah2[1] = U32(&PSH_(wid, g + 8, c));     al2[1] = U32(&PSL_(wid, g + 8, c));
            ah2[2] = U32(&PSH_(wid, g, c + 8));     al2[2] = U32(&PSL_(wid, g, c + 8));
            ah2[3] = U32(&PSH_(wid, g + 8, c + 8)); al2[3] = U32(&PSL_(wid, g + 8, c + 8));
#pragma unroll
            for (int vt = 0; vt < 3; vt++) {
                const int row = vt * 8 + g;
                uint32_t vbh[2] = { U32(&VTH_(st, row, c)), U32(&VTH_(st, row, c + 8)) };
                uint32_t vbl[2] = { U32(&VTL_(st, row, c)), U32(&VTL_(st, row, c + 8)) };
                mma_bf16(o[vt], ah2, vbh);
                mma_bf16(o[vt], al2, vbh);
                mma_bf16(o[vt], ah2, vbl);
            }
        }
        __syncthreads();   // protect KV/Ps buffers before next iteration
    }

    float inv0 = 1.f / lrow0;
    float inv1 = 1.f / lrow1;
    int tq = q0 + wid * 16 + g;
    int b_ = bh >> 5, hh = bh & 31;
#pragma unroll
    for (int vt = 0; vt < 3; vt++) {
        int col = hh * 24 + vt * 8 + 2 * t;
        float *d0 = &g_attn[((size_t)tq * 16 + b_) * 768 + col];
        d0[0] = o[vt][0] * inv0;
        d0[1] = o[vt][1] * inv0;
        float *d1 = &g_attn[((size_t)(tq + 8) * 16 + b_) * 768 + col];
        d1[0] = o[vt][2] * inv1;
        d1[1] = o[vt][3] * inv1;
    }
}

// ---------------------------------------------------------------------------
extern "C" void kernel_launch(void *const *d_in, const int *in_sizes, int n_in,
                              void *d_out, int out_size)
{
    const float *query = (const float *)d_in[0];
    const float *attn_bias = (const float *)d_in[1];
    const float *Wq = (const float *)d_in[2];
    const float *bq = (const float *)d_in[3];
    const float *Wk = (const float *)d_in[4];
    const float *bk = (const float *)d_in[5];
    const float *Wv = (const float *)d_in[6];
    const float *bv = (const float *)d_in[7];
    const float *Wo = (const float *)d_in[8];
    const float *bo = (const float *)d_in[9];
    float *out = (float *)d_out;

    cudaFuncSetAttribute(attn_kernel, cudaFuncAttributeMaxDynamicSharedMemorySize,
                         ATTN_SMEM_BYTES);

    // split X and weights into bf16 hi/lo planes
    split_query<<<6144, 256>>>(query);
    split_w<<<dim3(576, 4), 256>>>(Wq, Wk, Wv, Wo);

    // QKV projection (bf16x3)
    gemm3x<0><<<dim3(12, 64, 3), 256>>>(bq, bk, bv, nullptr);

    // fused attention (bf16x3): 512 heads x 4 q-tiles of 128 rows
    attn_kernel<<<dim3(512, 4), 256, ATTN_SMEM_BYTES>>>(attn_bias);

    // re-split attention output
    split_attnout<<<6144, 256>>>();

    // output projection
    gemm3x<1><<<dim3(12, 64, 1), 256>>>(bo, nullptr, nullptr, out);
}

// round 16
// speedup vs baseline: 1.7172x; 1.1068x over previous
#include <cuda_runtime.h>
#include <cuda_bf16.h>
#include <cstdint>
#include <cstddef>

// T=512, B=16, E=768, H=32, d=24, BH=512, M=T*B=8192
#define LOG2E 1.4426950408889634f

// ---------------------------------------------------------------------------
// Global scratch (zero-initialized __device__ globals; referenced ONLY in
// device code)
// ---------------------------------------------------------------------------
__device__ __nv_bfloat16 g_xh[8192 * 768];        // X / attn-out hi plane
__device__ __nv_bfloat16 g_xl[8192 * 768];        // lo plane
__device__ __nv_bfloat16 g_wh[4 * 768 * 768];     // W{q,k,v,o} hi planes
__device__ __nv_bfloat16 g_wl[4 * 768 * 768];
// Q,K planes [BH][T][32] (cols 24..31 stay zero forever), V transposed [BH][24][512]
__device__ __nv_bfloat16 g_qh[512 * 512 * 32];
__device__ __nv_bfloat16 g_ql[512 * 512 * 32];
__device__ __nv_bfloat16 g_kh[512 * 512 * 32];
__device__ __nv_bfloat16 g_kl[512 * 512 * 32];
__device__ __nv_bfloat16 g_vh[512 * 24 * 512];
__device__ __nv_bfloat16 g_vl[512 * 24 * 512];
__device__ float g_attn[8192 * 768];              // [T*B][E] fp32

// ---------------------------------------------------------------------------
// helpers
// ---------------------------------------------------------------------------
__device__ __forceinline__ uint32_t bpack(float hi, float lo) {
    uint32_t r;
    asm("cvt.rn.bf16x2.f32 %0, %1, %2;" : "=r"(r) : "f"(hi), "f"(lo));
    return r;
}
__device__ __forceinline__ void bsplit2(float x0, float x1, uint32_t &h, uint32_t &l) {
    h = bpack(x1, x0);
    float r0 = x0 - __uint_as_float(h << 16);
    float r1 = x1 - __uint_as_float(h & 0xffff0000u);
    l = bpack(r1, r0);
}
__device__ __forceinline__ void mma_bf16(float *c, const uint32_t *a, const uint32_t *b) {
    asm volatile(
        "mma.sync.aligned.m16n8k16.row.col.f32.bf16.bf16.f32 "
        "{%0,%1,%2,%3}, {%4,%5,%6,%7}, {%8,%9}, {%0,%1,%2,%3};"
        : "+f"(c[0]), "+f"(c[1]), "+f"(c[2]), "+f"(c[3])
        : "r"(a[0]), "r"(a[1]), "r"(a[2]), "r"(a[3]), "r"(b[0]), "r"(b[1]));
}
__device__ __forceinline__ void cpa16(void *s, const void *g) {
    uint32_t sa = (uint32_t)__cvta_generic_to_shared(s);
    asm volatile("cp.async.cg.shared.global [%0], [%1], 16;" :: "r"(sa), "l"(g));
}
__device__ __forceinline__ uint32_t U32(const __nv_bfloat16 *p) {
    return *(const uint32_t *)p;
}
__device__ __forceinline__ void ldsm4(uint32_t *r, const __nv_bfloat16 *p) {
    uint32_t a = (uint32_t)__cvta_generic_to_shared(p);
    asm volatile("ldmatrix.sync.aligned.m8n8.x4.shared.b16 {%0,%1,%2,%3}, [%4];"
                 : "=r"(r[0]), "=r"(r[1]), "=r"(r[2]), "=r"(r[3]) : "r"(a));
}
__device__ __forceinline__ void ldsm2(uint32_t *r, const __nv_bfloat16 *p) {
    uint32_t a = (uint32_t)__cvta_generic_to_shared(p);
    asm volatile("ldmatrix.sync.aligned.m8n8.x2.shared.b16 {%0,%1}, [%2];"
                 : "=r"(r[0]), "=r"(r[1]) : "r"(a));
}
__device__ __forceinline__ void stsm4(__nv_bfloat16 *p, uint32_t r0, uint32_t r1,
                                      uint32_t r2, uint32_t r3) {
    uint32_t a = (uint32_t)__cvta_generic_to_shared(p);
    asm volatile("stmatrix.sync.aligned.m8n8.x4.shared.b16 [%0], {%1,%2,%3,%4};"
                 :: "r"(a), "r"(r0), "r"(r1), "r"(r2), "r"(r3) : "memory");
}

// ---------------------------------------------------------------------------
// Split kernels: fp32 -> (bf16 hi, lo) planes
// ---------------------------------------------------------------------------
__global__ __launch_bounds__(256) void split_query(const float *__restrict__ src)
{
    size_t i = ((size_t)blockIdx.x * 256 + threadIdx.x) * 4;
    float4 v = *(const float4 *)(src + i);
    uint32_t h01, l01, h23, l23;
    bsplit2(v.x, v.y, h01, l01);
    bsplit2(v.z, v.w, h23, l23);
    *(uint2 *)&g_xh[i] = make_uint2(h01, h23);
    *(uint2 *)&g_xl[i] = make_uint2(l01, l23);
}

__global__ __launch_bounds__(256) void split_attnout()
{
    size_t i = ((size_t)blockIdx.x * 256 + threadIdx.x) * 4;
    float4 v = *(const float4 *)(g_attn + i);
    uint32_t h01, l01, h23, l23;
    bsplit2(v.x, v.y, h01, l01);
    bsplit2(v.z, v.w, h23, l23);
    *(uint2 *)&g_xh[i] = make_uint2(h01, h23);
    *(uint2 *)&g_xl[i] = make_uint2(l01, l23);
}

__global__ __launch_bounds__(256) void split_w(
    const float *__restrict__ w0, const float *__restrict__ w1,
    const float *__restrict__ w2, const float *__restrict__ w3)
{
    int mat = blockIdx.y;
    const float *src = (mat == 0) ? w0 : (mat == 1) ? w1 : (mat == 2) ? w2 : w3;
    size_t i = ((size_t)blockIdx.x * 256 + threadIdx.x) * 4;
    float4 v = *(const float4 *)(src + i);
    size_t o = (size_t)mat * (768 * 768) + i;
    uint32_t h01, l01, h23, l23;
    bsplit2(v.x, v.y, h01, l01);
    bsplit2(v.z, v.w, h23, l23);
    *(uint2 *)&g_wh[o] = make_uint2(h01, h23);
    *(uint2 *)&g_wl[o] = make_uint2(l01, l23);
}

// ---------------------------------------------------------------------------
// GEMM: C[M,N] = A[M,K] @ W[N,K]^T + bias, 3xBF16 (m16n8k16), ldmatrix,
// BM=128 BN=64 BK=32, 2-stage cp.async double buffer in 60KB dynamic SMEM.
// Layout (bf16 elems): AH@0 [2][128][40], AL@10240, BH@20480 [2][64][40], BL@25600
// ---------------------------------------------------------------------------
#define GEMM_SMEM_BYTES (30720 * 2)
#define GAH(st, r, c) smg[(st) * 5120 + (r) * 40 + (c)]
#define GAL(st, r, c) smg[10240 + (st) * 5120 + (r) * 40 + (c)]
#define GBH(st, r, c) smg[20480 + (st) * 2560 + (r) * 40 + (c)]
#define GBL(st, r, c) smg[25600 + (st) * 2560 + (r) * 40 + (c)]

template <int MODE>
__global__ __launch_bounds__(256, 2) void gemm3x(
    const float *__restrict__ bias0, const float *__restrict__ bias1,
    const float *__restrict__ bias2, float *__restrict__ outp)
{
    extern __shared__ __nv_bfloat16 smg[];

    const int tid = threadIdx.x;
    const int lane = tid & 31, wid = tid >> 5;
    const int g = lane >> 2, t = lane & 3;
    const int wm = wid & 3, wn = wid >> 2;
    const int m0 = blockIdx.y * 128, n0 = blockIdx.x * 64;
    const int mat = (MODE == 0) ? (int)blockIdx.z : 3;

    // ldmatrix per-lane address components
    const int lrA = (lane & 7) + ((lane >> 3) & 1) * 8;   // A-tile row, m-order (r,r+8,c+8)
    const int lcA = (lane >> 4) * 8;                      // A-tile col
    const int brB = (lane >> 4) * 8 + (lane & 7);         // B-tile row (2 n-blocks)
    const int bcB = ((lane >> 3) & 1) * 8;                // B-tile col

    const float *bias = (MODE == 0)
        ? ((mat == 0) ? bias0 : (mat == 1) ? bias1 : bias2) : bias0;
    const float scale = (MODE == 0 && mat == 0) ? 0.2041241452319315f : 1.0f;

    const __nv_bfloat16 *Wh = g_wh + (size_t)mat * (768 * 768);
    const __nv_bfloat16 *Wl = g_wl + (size_t)mat * (768 * 768);

    auto load_slab = [&](int kk, int st) {
#pragma unroll
        for (int i = 0; i < 2; i++) {
            int idx = tid + i * 256;
            int r = idx >> 2, c8 = (idx & 3) * 8;
            size_t go = (size_t)(m0 + r) * 768 + kk + c8;
            cpa16(&GAH(st, r, c8), g_xh + go);
            cpa16(&GAL(st, r, c8), g_xl + go);
        }
        {
            int r = tid >> 2, c8 = (tid & 3) * 8;
            size_t go = (size_t)(n0 + r) * 768 + kk + c8;
            cpa16(&GBH(st, r, c8), Wh + go);
            cpa16(&GBL(st, r, c8), Wl + go);
        }
        asm volatile("cp.async.commit_group;");
    };

    float c[2][4][4];
#pragma unroll
    for (int mt = 0; mt < 2; mt++)
#pragma unroll
        for (int nt = 0; nt < 4; nt++)
#pragma unroll
            for (int j = 0; j < 4; j++) c[mt][nt][j] = 0.f;

    load_slab(0, 0);

    const int NIT = 24;
    for (int it = 0; it < NIT; it++) {
        const int st = it & 1;
        if (it + 1 < NIT) {
            load_slab((it + 1) * 32, st ^ 1);
            asm volatile("cp.async.wait_group 1;");
        } else {
            asm volatile("cp.async.wait_group 0;");
        }
        __syncthreads();

#pragma unroll
        for (int ks = 0; ks < 32; ks += 16) {
            uint32_t ah[2][4], al[2][4], bh[4][2], bl[4][2];
#pragma unroll
            for (int mt = 0; mt < 2; mt++) {
                int r = wm * 32 + mt * 16 + lrA;
                ldsm4(ah[mt], &GAH(st, r, ks + lcA));
                ldsm4(al[mt], &GAL(st, r, ks + lcA));
            }
#pragma unroll
            for (int np = 0; np < 2; np++) {
                int n = wn * 32 + np * 16 + brB;
                uint32_t tb[4];
                ldsm4(tb, &GBH(st, n, ks + bcB));
                bh[2 * np][0] = tb[0]; bh[2 * np][1] = tb[1];
                bh[2 * np + 1][0] = tb[2]; bh[2 * np + 1][1] = tb[3];
                ldsm4(tb, &GBL(st, n, ks + bcB));
                bl[2 * np][0] = tb[0]; bl[2 * np][1] = tb[1];
                bl[2 * np + 1][0] = tb[2]; bl[2 * np + 1][1] = tb[3];
            }
#pragma unroll
            for (int mt = 0; mt < 2; mt++)
#pragma unroll
                for (int nt = 0; nt < 4; nt++) {
                    mma_bf16(c[mt][nt], ah[mt], bh[nt]);
                    mma_bf16(c[mt][nt], al[mt], bh[nt]);
                    mma_bf16(c[mt][nt], ah[mt], bl[nt]);
                }
        }
        __syncthreads();
    }

#pragma unroll
    for (int mt = 0; mt < 2; mt++) {
#pragma unroll
        for (int nt = 0; nt < 4; nt++) {
#pragma unroll
            for (int j = 0; j < 4; j++) {
                int m = m0 + wm * 32 + mt * 16 + g + ((j >> 1) ? 8 : 0);
                int n = n0 + wn * 32 + nt * 8 + 2 * t + (j & 1);
                float v = (c[mt][nt][j] + bias[n]) * scale;
                if (MODE == 0) {
                    int tt = m >> 4, bb = m & 15;           // m = t*16 + b
                    int h = n / 24, dd = n - h * 24;        // n = h*24 + dd
                    __nv_bfloat16 hb = __float2bfloat16(v);
                    __nv_bfloat16 lb = __float2bfloat16(v - __bfloat162float(hb));
                    if (mat == 2) {   // V transposed [BH][24][512]
                        size_t idx = (((size_t)bb * 32 + h) * 24 + dd) * 512 + tt;
                        g_vh[idx] = hb; g_vl[idx] = lb;
                    } else {          // Q/K [BH][T][32]
                        size_t idx = (((size_t)bb * 32 + h) * 512 + tt) * 32 + dd;
                        if (mat == 0) { g_qh[idx] = hb; g_ql[idx] = lb; }
                        else          { g_kh[idx] = hb; g_kl[idx] = lb; }
                    }
                } else {
                    outp[(size_t)m * 768 + n] = v;
                }
            }
        }
    }
}

// ---------------------------------------------------------------------------
// Fused attention, 3xBF16 + ldmatrix/stmatrix. 256 threads, 128 q-rows/CTA.
// SMEM layout identical to R15 (91,648 B).
// ---------------------------------------------------------------------------
#define ATTN_SMEM_BYTES (45824 * 2)
#define QH_(r, c)      smb[(r) * 40 + (c)]
#define QL_(r, c)      smb[5120 + (r) * 40 + (c)]
#define KH_(st, r, c)  smb[10240 + ((st) * 64 + (r)) * 40 + (c)]
#define KL_(st, r, c)  smb[15360 + ((st) * 64 + (r)) * 40 + (c)]
#define VTH_(st, r, c) smb[20480 + ((st) * 24 + (r)) * 72 + (c)]
#define VTL_(st, r, c) smb[23936 + ((st) * 24 + (r)) * 72 + (c)]
#define PSH_(w, r, c)  smb[27392 + ((w) * 16 + (r)) * 72 + (c)]
#define PSL_(w, r, c)  smb[36608 + ((w) * 16 + (r)) * 72 + (c)]

__global__ __launch_bounds__(256) void attn_kernel(const float *__restrict__ biasG)
{
    extern __shared__ __nv_bfloat16 smb[];

    const int tid = threadIdx.x;
    const int lane = tid & 31, wid = tid >> 5;
    const int g = lane >> 2, t = lane & 3;
    const int bh = blockIdx.x;
    const int q0 = blockIdx.y * 128;

    const int lrA = (lane & 7) + ((lane >> 3) & 1) * 8;
    const int lcA = (lane >> 4) * 8;
    const int brB = (lane >> 4) * 8 + (lane & 7);
    const int bcB = ((lane >> 3) & 1) * 8;

    const size_t hqk = (size_t)bh * (512 * 32);
    const size_t hv = (size_t)bh * (24 * 512);
    const float *Bp = biasG + (size_t)bh * (512 * 512);

    // Q planes: 128 rows x 32 bf16 = 512 granules per plane
    for (int i = tid; i < 512; i += 256) {
        int r = i >> 2, c8 = (i & 3) * 8;
        size_t go = hqk + (size_t)(q0 + r) * 32 + c8;
        cpa16(&QH_(r, c8), g_qh + go);
        cpa16(&QL_(r, c8), g_ql + go);
    }
    asm volatile("cp.async.commit_group;");

    auto ldkv = [&](int s0, int st) {
        {
            int r = tid >> 2, c8 = (tid & 3) * 8;
            size_t go = hqk + (size_t)(s0 + r) * 32 + c8;
            cpa16(&KH_(st, r, c8), g_kh + go);
            cpa16(&KL_(st, r, c8), g_kl + go);
        }
        if (tid < 192) {
            int r = tid >> 3, c8 = (tid & 7) * 8;
            size_t go = hv + (size_t)r * 512 + s0 + c8;
            cpa16(&VTH_(st, r, c8), g_vh + go);
            cpa16(&VTL_(st, r, c8), g_vl + go);
        }
        asm volatile("cp.async.commit_group;");
    };

    ldkv(0, 0);
    asm volatile("cp.async.wait_group 1;");   // Q done (KV0 may be pending)
    __syncthreads();

    // Q fragments are loop-invariant: 2 k16-steps cover d=24 (pad zero)
    uint32_t qh[2][4], ql[2][4];
    {
        int r = wid * 16 + lrA;
#pragma unroll
        for (int ks = 0; ks < 2; ks++) {
            ldsm4(qh[ks], &QH_(r, ks * 16 + lcA));
            ldsm4(ql[ks], &QL_(r, ks * 16 + lcA));
        }
    }

    float mrow0 = -1e30f, mrow1 = -1e30f;
    float lrow0 = 0.f, lrow1 = 0.f;
    float o[3][4];
#pragma unroll
    for (int vt = 0; vt < 3; vt++)
#pragma unroll
        for (int j = 0; j < 4; j++) o[vt][j] = 0.f;

    const int rg0 = q0 + wid * 16 + g;

    for (int it = 0; it < 8; it++) {
        const int st = it & 1;
        const int s0 = it * 64;
        if (it + 1 < 8) {
            ldkv((it + 1) * 64, st ^ 1);
            asm volatile("cp.async.wait_group 1;");
        } else {
            asm volatile("cp.async.wait_group 0;");
        }
        __syncthreads();

        // bias -> accumulator init
        float s[8][4];
        const float *Bq0 = Bp + (size_t)rg0 * 512 + s0 + 2 * t;
        const float *Bq1 = Bp + (size_t)(rg0 + 8) * 512 + s0 + 2 * t;
#pragma unroll
        for (int nt = 0; nt < 8; nt++) {
            const float2 u0 = *(const float2 *)(Bq0 + nt * 8);
            const float2 u1 = *(const float2 *)(Bq1 + nt * 8);
            s[nt][0] = u0.x; s[nt][1] = u0.y;
            s[nt][2] = u1.x; s[nt][3] = u1.y;
        }

        // S += Q K^T (3xBF16, ldmatrix K)
#pragma unroll
        for (int ks = 0; ks < 2; ks++) {
            const int c0 = ks * 16;
#pragma unroll
            for (int np = 0; np < 4; np++) {
                uint32_t th[4], tl[4];
                ldsm4(th, &KH_(st, np * 16 + brB, c0 + bcB));
                ldsm4(tl, &KL_(st, np * 16 + brB, c0 + bcB));
                uint32_t b0h[2] = { th[0], th[1] }, b1h[2] = { th[2], th[3] };
                uint32_t b0l[2] = { tl[0], tl[1] }, b1l[2] = { tl[2], tl[3] };
                mma_bf16(s[2 * np],     qh[ks], b0h);
                mma_bf16(s[2 * np],     ql[ks], b0h);
                mma_bf16(s[2 * np],     qh[ks], b0l);
                mma_bf16(s[2 * np + 1], qh[ks], b1h);
                mma_bf16(s[2 * np + 1], ql[ks], b1h);
                mma_bf16(s[2 * np + 1], qh[ks], b1l);
            }
        }

        // online softmax (rows g, g+8 of this warp's 16-row slice)
        float tm0 = -1e30f, tm1 = -1e30f;
#pragma unroll
        for (int nt = 0; nt < 8; nt++) {
            tm0 = fmaxf(tm0, fmaxf(s[nt][0], s[nt][1]));
            tm1 = fmaxf(tm1, fmaxf(s[nt][2], s[nt][3]));
        }
        tm0 = fmaxf(tm0, __shfl_xor_sync(0xffffffffu, tm0, 1));
        tm0 = fmaxf(tm0, __shfl_xor_sync(0xffffffffu, tm0, 2));
        tm1 = fmaxf(tm1, __shfl_xor_sync(0xffffffffu, tm1, 1));
        tm1 = fmaxf(tm1, __shfl_xor_sync(0xffffffffu, tm1, 2));
        float mn0 = fmaxf(mrow0, tm0), mn1 = fmaxf(mrow1, tm1);
        float al0 = exp2f((mrow0 - mn0) * LOG2E);
        float al1 = exp2f((mrow1 - mn1) * LOG2E);
        float sum0 = 0.f, sum1 = 0.f;
#pragma unroll
        for (int nt = 0; nt < 8; nt++) {
            s[nt][0] = exp2f((s[nt][0] - mn0) * LOG2E);
            s[nt][1] = exp2f((s[nt][1] - mn0) * LOG2E);
            s[nt][2] = exp2f((s[nt][2] - mn1) * LOG2E);
            s[nt][3] = exp2f((s[nt][3] - mn1) * LOG2E);
            sum0 += s[nt][0] + s[nt][1];
            sum1 += s[nt][2] + s[nt][3];
        }
        sum0 += __shfl_xor_sync(0xffffffffu, sum0, 1);
        sum0 += __shfl_xor_sync(0xffffffffu, sum0, 2);
        sum1 += __shfl_xor_sync(0xffffffffu, sum1, 1);
        sum1 += __shfl_xor_sync(0xffffffffu, sum1, 2);
        lrow0 = lrow0 * al0 + sum0;
        lrow1 = lrow1 * al1 + sum1;
        mrow0 = mn0; mrow1 = mn1;
#pragma unroll
        for (int vt = 0; vt < 3; vt++) {
            o[vt][0] *= al0; o[vt][1] *= al0;
            o[vt][2] *= al1; o[vt][3] *= al1;
        }

        // P fragments -> SMEM hi/lo planes via stmatrix (per-warp region)
#pragma unroll
        for (int np = 0; np < 4; np++) {
            uint32_t h0, l0, h1, l1, h2, l2, h3, l3;
            bsplit2(s[2 * np][0],     s[2 * np][1],     h0, l0);
            bsplit2(s[2 * np][2],     s[2 * np][3],     h1, l1);
            bsplit2(s[2 * np + 1][0], s[2 * np + 1][1], h2, l2);
            bsplit2(s[2 * np + 1][2], s[2 * np + 1][3], h3, l3);
            stsm4(&PSH_(wid, lrA, np * 16 + lcA), h0, h1, h2, h3);
            stsm4(&PSL_(wid, lrA, np * 16 + lcA), l0, l1, l2, l3);
        }
        __syncwarp();

        // O += P V (3xBF16, ldmatrix P and V)
#pragma unroll
        for (int ks = 0; ks < 4; ks++) {
            const int c0 = ks * 16;
            uint32_t ah2[4], al2[4];
            ldsm4(ah2, &PSH_(wid, lrA, c0 + lcA));
            ldsm4(al2, &PSL_(wid, lrA, c0 + lcA));
            uint32_t vh01[4], vl01[4], vh2[2], vl2[2];
            ldsm4(vh01, &VTH_(st, brB, c0 + bcB));
            ldsm4(vl01, &VTL_(st, brB, c0 + bcB));
            ldsm2(vh2, &VTH_(st, 16 + (lane & 7), c0 + bcB));
            ldsm2(vl2, &VTL_(st, 16 + (lane & 7), c0 + bcB));
            uint32_t v0h[2] = { vh01[0], vh01[1] }, v1h[2] = { vh01[2], vh01[3] };
            uint32_t v0l[2] = { vl01[0], vl01[1] }, v1l[2] = { vl01[2], vl01[3] };
            mma_bf16(o[0], ah2, v0h); mma_bf16(o[0], al2, v0h); mma_bf16(o[0], ah2, v0l);
            mma_bf16(o[1], ah2, v1h); mma_bf16(o[1], al2, v1h); mma_bf16(o[1], ah2, v1l);
            mma_bf16(o[2], ah2, vh2); mma_bf16(o[2], al2, vh2); mma_bf16(o[2], ah2, vl2);
        }
        __syncthreads();   // protect KV/Ps buffers before next iteration
    }

    float inv0 = 1.f / lrow0;
    float inv1 = 1.f / lrow1;
    int tq = q0 + wid * 16 + g;
    int b_ = bh >> 5, hh = bh & 31;
#pragma unroll
    for (int vt = 0; vt < 3; vt++) {
        int col = hh * 24 + vt * 8 + 2 * t;
        float *d0 = &g_attn[((size_t)tq * 16 + b_) * 768 + col];
        d0[0] = o[vt][0] * inv0;
        d0[1] = o[vt][1] * inv0;
        float *d1 = &g_attn[((size_t)(tq + 8) * 16 + b_) * 768 + col];
        d1[0] = o[vt][2] * inv1;
        d1[1] = o[vt][3] * inv1;
    }
}

// ---------------------------------------------------------------------------
extern "C" void kernel_launch(void *const *d_in, const int *in_sizes, int n_in,
                              void *d_out, int out_size)
{
    const float *query = (const float *)d_in[0];
    const float *attn_bias = (const float *)d_in[1];
    const float *Wq = (const float *)d_in[2];
    const float *bq = (const float *)d_in[3];
    const float *Wk = (const float *)d_in[4];
    const float *bk = (const float *)d_in[5];
    const float *Wv = (const float *)d_in[6];
    const float *bv = (const float *)d_in[7];
    const float *Wo = (const float *)d_in[8];
    const float *bo = (const float *)d_in[9];
    float *out = (float *)d_out;

    cudaFuncSetAttribute(attn_kernel, cudaFuncAttributeMaxDynamicSharedMemorySize,
                         ATTN_SMEM_BYTES);
    cudaFuncSetAttribute(gemm3x<0>, cudaFuncAttributeMaxDynamicSharedMemorySize,
                         GEMM_SMEM_BYTES);
    cudaFuncSetAttribute(gemm3x<1>, cudaFuncAttributeMaxDynamicSharedMemorySize,
                         GEMM_SMEM_BYTES);

    // split X and weights into bf16 hi/lo planes
    split_query<<<6144, 256>>>(query);
    split_w<<<dim3(576, 4), 256>>>(Wq, Wk, Wv, Wo);

    // QKV projection (bf16x3, ldmatrix, double-buffered)
    gemm3x<0><<<dim3(12, 64, 3), 256, GEMM_SMEM_BYTES>>>(bq, bk, bv, nullptr);

    // fused attention (bf16x3): 512 heads x 4 q-tiles of 128 rows
    attn_kernel<<<dim3(512, 4), 256, ATTN_SMEM_BYTES>>>(attn_bias);

    // re-split attention output
    split_attnout<<<6144, 256>>>();

    // output projection
    gemm3x<1><<<dim3(12, 64, 1), 256, GEMM_SMEM_BYTES>>>(bo, nullptr, nullptr, out);
}

// round 17
// speedup vs baseline: 1.8471x; 1.0756x over previous
#include <cuda_runtime.h>
#include <cuda_bf16.h>
#include <cstdint>
#include <cstddef>

// T=512, B=16, E=768, H=32, d=24, BH=512, M=T*B=8192
#define LOG2E 1.4426950408889634f

// ---------------------------------------------------------------------------
// Global scratch (zero-initialized __device__ globals; referenced ONLY in
// device code)
// ---------------------------------------------------------------------------
__device__ __nv_bfloat16 g_xh[8192 * 768];        // X / attn-out hi plane
__device__ __nv_bfloat16 g_xl[8192 * 768];        // lo plane
__device__ __nv_bfloat16 g_wh[4 * 768 * 768];     // W{q,k,v,o} hi planes
__device__ __nv_bfloat16 g_wl[4 * 768 * 768];
// Q,K planes [BH][T][32] (cols 24..31 stay zero forever), V transposed [BH][24][512]
__device__ __nv_bfloat16 g_qh[512 * 512 * 32];
__device__ __nv_bfloat16 g_ql[512 * 512 * 32];
__device__ __nv_bfloat16 g_kh[512 * 512 * 32];
__device__ __nv_bfloat16 g_kl[512 * 512 * 32];
__device__ __nv_bfloat16 g_vh[512 * 24 * 512];
__device__ __nv_bfloat16 g_vl[512 * 24 * 512];

// ---------------------------------------------------------------------------
// helpers
// ---------------------------------------------------------------------------
__device__ __forceinline__ uint32_t bpack(float hi, float lo) {
    uint32_t r;
    asm("cvt.rn.bf16x2.f32 %0, %1, %2;" : "=r"(r) : "f"(hi), "f"(lo));
    return r;
}
__device__ __forceinline__ void bsplit2(float x0, float x1, uint32_t &h, uint32_t &l) {
    h = bpack(x1, x0);
    float r0 = x0 - __uint_as_float(h << 16);
    float r1 = x1 - __uint_as_float(h & 0xffff0000u);
    l = bpack(r1, r0);
}
__device__ __forceinline__ void mma_bf16(float *c, const uint32_t *a, const uint32_t *b) {
    asm volatile(
        "mma.sync.aligned.m16n8k16.row.col.f32.bf16.bf16.f32 "
        "{%0,%1,%2,%3}, {%4,%5,%6,%7}, {%8,%9}, {%0,%1,%2,%3};"
        : "+f"(c[0]), "+f"(c[1]), "+f"(c[2]), "+f"(c[3])
        : "r"(a[0]), "r"(a[1]), "r"(a[2]), "r"(a[3]), "r"(b[0]), "r"(b[1]));
}
__device__ __forceinline__ void cpa16(void *s, const void *g) {
    uint32_t sa = (uint32_t)__cvta_generic_to_shared(s);
    asm volatile("cp.async.cg.shared.global [%0], [%1], 16;" :: "r"(sa), "l"(g));
}
__device__ __forceinline__ void ldsm4(uint32_t *r, const __nv_bfloat16 *p) {
    uint32_t a = (uint32_t)__cvta_generic_to_shared(p);
    asm volatile("ldmatrix.sync.aligned.m8n8.x4.shared.b16 {%0,%1,%2,%3}, [%4];"
                 : "=r"(r[0]), "=r"(r[1]), "=r"(r[2]), "=r"(r[3]) : "r"(a));
}
__device__ __forceinline__ void ldsm2(uint32_t *r, const __nv_bfloat16 *p) {
    uint32_t a = (uint32_t)__cvta_generic_to_shared(p);
    asm volatile("ldmatrix.sync.aligned.m8n8.x2.shared.b16 {%0,%1}, [%2];"
                 : "=r"(r[0]), "=r"(r[1]) : "r"(a));
}

// ---------------------------------------------------------------------------
// Split kernels: fp32 -> (bf16 hi, lo) planes
// ---------------------------------------------------------------------------
__global__ __launch_bounds__(256) void split_query(const float *__restrict__ src)
{
    size_t i = ((size_t)blockIdx.x * 256 + threadIdx.x) * 4;
    float4 v = *(const float4 *)(src + i);
    uint32_t h01, l01, h23, l23;
    bsplit2(v.x, v.y, h01, l01);
    bsplit2(v.z, v.w, h23, l23);
    *(uint2 *)&g_xh[i] = make_uint2(h01, h23);
    *(uint2 *)&g_xl[i] = make_uint2(l01, l23);
}

__global__ __launch_bounds__(256) void split_w(
    const float *__restrict__ w0, const float *__restrict__ w1,
    const float *__restrict__ w2, const float *__restrict__ w3)
{
    int mat = blockIdx.y;
    const float *src = (mat == 0) ? w0 : (mat == 1) ? w1 : (mat == 2) ? w2 : w3;
    size_t i = ((size_t)blockIdx.x * 256 + threadIdx.x) * 4;
    float4 v = *(const float4 *)(src + i);
    size_t o = (size_t)mat * (768 * 768) + i;
    uint32_t h01, l01, h23, l23;
    bsplit2(v.x, v.y, h01, l01);
    bsplit2(v.z, v.w, h23, l23);
    *(uint2 *)&g_wh[o] = make_uint2(h01, h23);
    *(uint2 *)&g_wl[o] = make_uint2(l01, l23);
}

// ---------------------------------------------------------------------------
// GEMM: C[M,N] = A[M,K] @ W[N,K]^T + bias, 3xBF16 (m16n8k16), ldmatrix,
// BM=128 BN=64 BK=32, 2-stage cp.async double buffer in 60KB dynamic SMEM.
// ---------------------------------------------------------------------------
#define GEMM_SMEM_BYTES (30720 * 2)
#define GAH(st, r, c) smg[(st) * 5120 + (r) * 40 + (c)]
#define GAL(st, r, c) smg[10240 + (st) * 5120 + (r) * 40 + (c)]
#define GBH(st, r, c) smg[20480 + (st) * 2560 + (r) * 40 + (c)]
#define GBL(st, r, c) smg[25600 + (st) * 2560 + (r) * 40 + (c)]

template <int MODE>
__global__ __launch_bounds__(256, 2) void gemm3x(
    const float *__restrict__ bias0, const float *__restrict__ bias1,
    const float *__restrict__ bias2, float *__restrict__ outp)
{
    extern __shared__ __nv_bfloat16 smg[];

    const int tid = threadIdx.x;
    const int lane = tid & 31, wid = tid >> 5;
    const int g = lane >> 2, t = lane & 3;
    const int wm = wid & 3, wn = wid >> 2;
    const int m0 = blockIdx.y * 128, n0 = blockIdx.x * 64;
    const int mat = (MODE == 0) ? (int)blockIdx.z : 3;

    const int lrA = (lane & 7) + ((lane >> 3) & 1) * 8;
    const int lcA = (lane >> 4) * 8;
    const int brB = (lane >> 4) * 8 + (lane & 7);
    const int bcB = ((lane >> 3) & 1) * 8;

    const float *bias = (MODE == 0)
        ? ((mat == 0) ? bias0 : (mat == 1) ? bias1 : bias2) : bias0;
    const float scale = (MODE == 0 && mat == 0) ? 0.2041241452319315f : 1.0f;

    const __nv_bfloat16 *Wh = g_wh + (size_t)mat * (768 * 768);
    const __nv_bfloat16 *Wl = g_wl + (size_t)mat * (768 * 768);

    auto load_slab = [&](int kk, int st) {
#pragma unroll
        for (int i = 0; i < 2; i++) {
            int idx = tid + i * 256;
            int r = idx >> 2, c8 = (idx & 3) * 8;
            size_t go = (size_t)(m0 + r) * 768 + kk + c8;
            cpa16(&GAH(st, r, c8), g_xh + go);
            cpa16(&GAL(st, r, c8), g_xl + go);
        }
        {
            int r = tid >> 2, c8 = (tid & 3) * 8;
            size_t go = (size_t)(n0 + r) * 768 + kk + c8;
            cpa16(&GBH(st, r, c8), Wh + go);
            cpa16(&GBL(st, r, c8), Wl + go);
        }
        asm volatile("cp.async.commit_group;");
    };

    float c[2][4][4];
#pragma unroll
    for (int mt = 0; mt < 2; mt++)
#pragma unroll
        for (int nt = 0; nt < 4; nt++)
#pragma unroll
            for (int j = 0; j < 4; j++) c[mt][nt][j] = 0.f;

    load_slab(0, 0);

    const int NIT = 24;
    for (int it = 0; it < NIT; it++) {
        const int st = it & 1;
        if (it + 1 < NIT) {
            load_slab((it + 1) * 32, st ^ 1);
            asm volatile("cp.async.wait_group 1;");
        } else {
            asm volatile("cp.async.wait_group 0;");
        }
        __syncthreads();

#pragma unroll
        for (int ks = 0; ks < 32; ks += 16) {
            uint32_t ah[2][4], al[2][4], bh[4][2], bl[4][2];
#pragma unroll
            for (int mt = 0; mt < 2; mt++) {
                int r = wm * 32 + mt * 16 + lrA;
                ldsm4(ah[mt], &GAH(st, r, ks + lcA));
                ldsm4(al[mt], &GAL(st, r, ks + lcA));
            }
#pragma unroll
            for (int np = 0; np < 2; np++) {
                int n = wn * 32 + np * 16 + brB;
                uint32_t tb[4];
                ldsm4(tb, &GBH(st, n, ks + bcB));
                bh[2 * np][0] = tb[0]; bh[2 * np][1] = tb[1];
                bh[2 * np + 1][0] = tb[2]; bh[2 * np + 1][1] = tb[3];
                ldsm4(tb, &GBL(st, n, ks + bcB));
                bl[2 * np][0] = tb[0]; bl[2 * np][1] = tb[1];
                bl[2 * np + 1][0] = tb[2]; bl[2 * np + 1][1] = tb[3];
            }
#pragma unroll
            for (int mt = 0; mt < 2; mt++)
#pragma unroll
                for (int nt = 0; nt < 4; nt++) {
                    mma_bf16(c[mt][nt], ah[mt], bh[nt]);
                    mma_bf16(c[mt][nt], al[mt], bh[nt]);
                    mma_bf16(c[mt][nt], ah[mt], bl[nt]);
                }
        }
        __syncthreads();
    }

#pragma unroll
    for (int mt = 0; mt < 2; mt++) {
#pragma unroll
        for (int nt = 0; nt < 4; nt++) {
#pragma unroll
            for (int j = 0; j < 4; j++) {
                int m = m0 + wm * 32 + mt * 16 + g + ((j >> 1) ? 8 : 0);
                int n = n0 + wn * 32 + nt * 8 + 2 * t + (j & 1);
                float v = (c[mt][nt][j] + bias[n]) * scale;
                if (MODE == 0) {
                    int tt = m >> 4, bb = m & 15;           // m = t*16 + b
                    int h = n / 24, dd = n - h * 24;        // n = h*24 + dd
                    __nv_bfloat16 hb = __float2bfloat16(v);
                    __nv_bfloat16 lb = __float2bfloat16(v - __bfloat162float(hb));
                    if (mat == 2) {   // V transposed [BH][24][512]
                        size_t idx = (((size_t)bb * 32 + h) * 24 + dd) * 512 + tt;
                        g_vh[idx] = hb; g_vl[idx] = lb;
                    } else {          // Q/K [BH][T][32]
                        size_t idx = (((size_t)bb * 32 + h) * 512 + tt) * 32 + dd;
                        if (mat == 0) { g_qh[idx] = hb; g_ql[idx] = lb; }
                        else          { g_kh[idx] = hb; g_kl[idx] = lb; }
                    }
                } else {
                    outp[(size_t)m * 768 + n] = v;
                }
            }
        }
    }
}

// ---------------------------------------------------------------------------
// Fused attention, 3xBF16. P stays in registers (C-fragments of two adjacent
// S-tiles ARE the A-fragment of PV). 256 threads, 128 q-rows/CTA.
// SMEM (bf16 elems): QH@0[128][40] QL@5120 KH@10240[2][64][40] KL@15360
//                    VTH@20480[2][24][72] VTL@23936  -> 27392 elems = 54784 B
// Epilogue writes bf16 hi/lo planes of attn-out directly (no fp32 staging).
// ---------------------------------------------------------------------------
#define ATTN_SMEM_BYTES (27392 * 2)
#define QH_(r, c)      smb[(r) * 40 + (c)]
#define QL_(r, c)      smb[5120 + (r) * 40 + (c)]
#define KH_(st, r, c)  smb[10240 + ((st) * 64 + (r)) * 40 + (c)]
#define KL_(st, r, c)  smb[15360 + ((st) * 64 + (r)) * 40 + (c)]
#define VTH_(st, r, c) smb[20480 + ((st) * 24 + (r)) * 72 + (c)]
#define VTL_(st, r, c) smb[23936 + ((st) * 24 + (r)) * 72 + (c)]

__global__ __launch_bounds__(256, 3) void attn_kernel(const float *__restrict__ biasG)
{
    extern __shared__ __nv_bfloat16 smb[];

    const int tid = threadIdx.x;
    const int lane = tid & 31, wid = tid >> 5;
    const int g = lane >> 2, t = lane & 3;
    const int bh = blockIdx.x;
    const int q0 = blockIdx.y * 128;

    const int lrA = (lane & 7) + ((lane >> 3) & 1) * 8;
    const int lcA = (lane >> 4) * 8;
    const int brB = (lane >> 4) * 8 + (lane & 7);
    const int bcB = ((lane >> 3) & 1) * 8;

    const size_t hqk = (size_t)bh * (512 * 32);
    const size_t hv = (size_t)bh * (24 * 512);
    const float *Bp = biasG + (size_t)bh * (512 * 512);

    // Q planes: 128 rows x 32 bf16 = 512 granules per plane
    for (int i = tid; i < 512; i += 256) {
        int r = i >> 2, c8 = (i & 3) * 8;
        size_t go = hqk + (size_t)(q0 + r) * 32 + c8;
        cpa16(&QH_(r, c8), g_qh + go);
        cpa16(&QL_(r, c8), g_ql + go);
    }
    asm volatile("cp.async.commit_group;");

    auto ldkv = [&](int s0, int st) {
        {
            int r = tid >> 2, c8 = (tid & 3) * 8;
            size_t go = hqk + (size_t)(s0 + r) * 32 + c8;
            cpa16(&KH_(st, r, c8), g_kh + go);
            cpa16(&KL_(st, r, c8), g_kl + go);
        }
        if (tid < 192) {
            int r = tid >> 3, c8 = (tid & 7) * 8;
            size_t go = hv + (size_t)r * 512 + s0 + c8;
            cpa16(&VTH_(st, r, c8), g_vh + go);
            cpa16(&VTL_(st, r, c8), g_vl + go);
        }
        asm volatile("cp.async.commit_group;");
    };

    ldkv(0, 0);
    asm volatile("cp.async.wait_group 1;");   // Q done (KV0 may be pending)
    __syncthreads();

    // Q fragments are loop-invariant: 2 k16-steps cover d=24 (pad zero)
    uint32_t qh[2][4], ql[2][4];
    {
        int r = wid * 16 + lrA;
#pragma unroll
        for (int ks = 0; ks < 2; ks++) {
            ldsm4(qh[ks], &QH_(r, ks * 16 + lcA));
            ldsm4(ql[ks], &QL_(r, ks * 16 + lcA));
        }
    }

    float mrow0 = -1e30f, mrow1 = -1e30f;
    float lrow0 = 0.f, lrow1 = 0.f;
    float o[3][4];
#pragma unroll
    for (int vt = 0; vt < 3; vt++)
#pragma unroll
        for (int j = 0; j < 4; j++) o[vt][j] = 0.f;

    const int rg0 = q0 + wid * 16 + g;

    for (int it = 0; it < 8; it++) {
        const int st = it & 1;
        const int s0 = it * 64;
        if (it + 1 < 8) {
            ldkv((it + 1) * 64, st ^ 1);
            asm volatile("cp.async.wait_group 1;");
        } else {
            asm volatile("cp.async.wait_group 0;");
        }
        __syncthreads();

        // bias -> accumulator init
        float s[8][4];
        const float *Bq0 = Bp + (size_t)rg0 * 512 + s0 + 2 * t;
        const float *Bq1 = Bp + (size_t)(rg0 + 8) * 512 + s0 + 2 * t;
#pragma unroll
        for (int nt = 0; nt < 8; nt++) {
            const float2 u0 = *(const float2 *)(Bq0 + nt * 8);
            const float2 u1 = *(const float2 *)(Bq1 + nt * 8);
            s[nt][0] = u0.x; s[nt][1] = u0.y;
            s[nt][2] = u1.x; s[nt][3] = u1.y;
        }

        // S += Q K^T (3xBF16, ldmatrix K)
#pragma unroll
        for (int ks = 0; ks < 2; ks++) {
            const int c0 = ks * 16;
#pragma unroll
            for (int np = 0; np < 4; np++) {
                uint32_t th[4], tl[4];
                ldsm4(th, &KH_(st, np * 16 + brB, c0 + bcB));
                ldsm4(tl, &KL_(st, np * 16 + brB, c0 + bcB));
                uint32_t b0h[2] = { th[0], th[1] }, b1h[2] = { th[2], th[3] };
                uint32_t b0l[2] = { tl[0], tl[1] }, b1l[2] = { tl[2], tl[3] };
                mma_bf16(s[2 * np],     qh[ks], b0h);
                mma_bf16(s[2 * np],     ql[ks], b0h);
                mma_bf16(s[2 * np],     qh[ks], b0l);
                mma_bf16(s[2 * np + 1], qh[ks], b1h);
                mma_bf16(s[2 * np + 1], ql[ks], b1h);
                mma_bf16(s[2 * np + 1], qh[ks], b1l);
            }
        }

        // online softmax (rows g, g+8 of this warp's 16-row slice)
        float tm0 = -1e30f, tm1 = -1e30f;
#pragma unroll
        for (int nt = 0; nt < 8; nt++) {
            tm0 = fmaxf(tm0, fmaxf(s[nt][0], s[nt][1]));
            tm1 = fmaxf(tm1, fmaxf(s[nt][2], s[nt][3]));
        }
        tm0 = fmaxf(tm0, __shfl_xor_sync(0xffffffffu, tm0, 1));
        tm0 = fmaxf(tm0, __shfl_xor_sync(0xffffffffu, tm0, 2));
        tm1 = fmaxf(tm1, __shfl_xor_sync(0xffffffffu, tm1, 1));
        tm1 = fmaxf(tm1, __shfl_xor_sync(0xffffffffu, tm1, 2));
        float mn0 = fmaxf(mrow0, tm0), mn1 = fmaxf(mrow1, tm1);
        float al0 = exp2f((mrow0 - mn0) * LOG2E);
        float al1 = exp2f((mrow1 - mn1) * LOG2E);
        float sum0 = 0.f, sum1 = 0.f;
#pragma unroll
        for (int nt = 0; nt < 8; nt++) {
            s[nt][0] = exp2f((s[nt][0] - mn0) * LOG2E);
            s[nt][1] = exp2f((s[nt][1] - mn0) * LOG2E);
            s[nt][2] = exp2f((s[nt][2] - mn1) * LOG2E);
            s[nt][3] = exp2f((s[nt][3] - mn1) * LOG2E);
            sum0 += s[nt][0] + s[nt][1];
            sum1 += s[nt][2] + s[nt][3];
        }
        sum0 += __shfl_xor_sync(0xffffffffu, sum0, 1);
        sum0 += __shfl_xor_sync(0xffffffffu, sum0, 2);
        sum1 += __shfl_xor_sync(0xffffffffu, sum1, 1);
        sum1 += __shfl_xor_sync(0xffffffffu, sum1, 2);
        lrow0 = lrow0 * al0 + sum0;
        lrow1 = lrow1 * al1 + sum1;
        mrow0 = mn0; mrow1 = mn1;
#pragma unroll
        for (int vt = 0; vt < 3; vt++) {
            o[vt][0] *= al0; o[vt][1] *= al0;
            o[vt][2] *= al1; o[vt][3] *= al1;
        }

        // O += P V : P A-fragments built directly from S C-fragments (registers)
#pragma unroll
        for (int ks = 0; ks < 4; ks++) {
            const int c0 = ks * 16;
            uint32_t ah2[4], al2[4];
            bsplit2(s[2 * ks][0],     s[2 * ks][1],     ah2[0], al2[0]);
            bsplit2(s[2 * ks][2],     s[2 * ks][3],     ah2[1], al2[1]);
            bsplit2(s[2 * ks + 1][0], s[2 * ks + 1][1], ah2[2], al2[2]);
            bsplit2(s[2 * ks + 1][2], s[2 * ks + 1][3], ah2[3], al2[3]);
            uint32_t vh01[4], vl01[4], vh2[2], vl2[2];
            ldsm4(vh01, &VTH_(st, brB, c0 + bcB));
            ldsm4(vl01, &VTL_(st, brB, c0 + bcB));
            ldsm2(vh2, &VTH_(st, 16 + (lane & 7), c0 + bcB));
            ldsm2(vl2, &VTL_(st, 16 + (lane & 7), c0 + bcB));
            uint32_t v0h[2] = { vh01[0], vh01[1] }, v1h[2] = { vh01[2], vh01[3] };
            uint32_t v0l[2] = { vl01[0], vl01[1] }, v1l[2] = { vl01[2], vl01[3] };
            mma_bf16(o[0], ah2, v0h); mma_bf16(o[0], al2, v0h); mma_bf16(o[0], ah2, v0l);
            mma_bf16(o[1], ah2, v1h); mma_bf16(o[1], al2, v1h); mma_bf16(o[1], ah2, v1l);
            mma_bf16(o[2], ah2, vh2); mma_bf16(o[2], al2, vh2); mma_bf16(o[2], ah2, vl2);
        }
        __syncthreads();   // protect KV buffers before next iteration
    }

    // Epilogue: write attn-out directly as bf16 hi/lo planes (fused split)
    float inv0 = 1.f / lrow0;
    float inv1 = 1.f / lrow1;
    int tq = q0 + wid * 16 + g;
    int b_ = bh >> 5, hh = bh & 31;
#pragma unroll
    for (int vt = 0; vt < 3; vt++) {
        int col = hh * 24 + vt * 8 + 2 * t;
        size_t i0 = ((size_t)tq * 16 + b_) * 768 + col;
        size_t i1 = ((size_t)(tq + 8) * 16 + b_) * 768 + col;
        uint32_t h, l;
        bsplit2(o[vt][0] * inv0, o[vt][1] * inv0, h, l);
        *(uint32_t *)&g_xh[i0] = h;
        *(uint32_t *)&g_xl[i0] = l;
        bsplit2(o[vt][2] * inv1, o[vt][3] * inv1, h, l);
        *(uint32_t *)&g_xh[i1] = h;
        *(uint32_t *)&g_xl[i1] = l;
    }
}

// ---------------------------------------------------------------------------
extern "C" void kernel_launch(void *const *d_in, const int *in_sizes, int n_in,
                              void *d_out, int out_size)
{
    const float *query = (const float *)d_in[0];
    const float *attn_bias = (const float *)d_in[1];
    const float *Wq = (const float *)d_in[2];
    const float *bq = (const float *)d_in[3];
    const float *Wk = (const float *)d_in[4];
    const float *bk = (const float *)d_in[5];
    const float *Wv = (const float *)d_in[6];
    const float *bv = (const float *)d_in[7];
    const float *Wo = (const float *)d_in[8];
    const float *bo = (const float *)d_in[9];
    float *out = (float *)d_out;

    cudaFuncSetAttribute(attn_kernel, cudaFuncAttributeMaxDynamicSharedMemorySize,
                         ATTN_SMEM_BYTES);
    cudaFuncSetAttribute(gemm3x<0>, cudaFuncAttributeMaxDynamicSharedMemorySize,
                         GEMM_SMEM_BYTES);
    cudaFuncSetAttribute(gemm3x<1>, cudaFuncAttributeMaxDynamicSharedMemorySize,
                         GEMM_SMEM_BYTES);

    // split X and weights into bf16 hi/lo planes
    split_query<<<6144, 256>>>(query);
    split_w<<<dim3(576, 4), 256>>>(Wq, Wk, Wv, Wo);

    // QKV projection (bf16x3, ldmatrix, double-buffered)
    gemm3x<0><<<dim3(12, 64, 3), 256, GEMM_SMEM_BYTES>>>(bq, bk, bv, nullptr);

    // fused attention (bf16x3): 512 heads x 4 q-tiles of 128 rows
    attn_kernel<<<dim3(512, 4), 256, ATTN_SMEM_BYTES>>>(attn_bias);

    // output projection (reads bf16 planes written by attention epilogue)
    gemm3x<1><<<dim3(12, 64, 1), 256, GEMM_SMEM_BYTES>>>(bo, nullptr, nullptr, out);
}